// round 1
// baseline (speedup 1.0000x reference)
#include <cuda_runtime.h>

#define N_NODES 50000
#define E_EDGES 800000
#define TOT_E   (E_EDGES + N_NODES)
#define DCH     128
#define EDIM    16

// ---------------- device scratch (no allocs allowed) ----------------
__device__ float g_xl[N_NODES * DCH];
__device__ float g_xr[N_NODES * DCH];
__device__ float g_zpre[N_NODES * DCH];
__device__ float g_z2[N_NODES * DCH];
__device__ float g_wext[384 * DCH];
__device__ int   g_deg[N_NODES];
__device__ int   g_cur[N_NODES];
__device__ int   g_off[N_NODES + 1];
__device__ int   g_elist[TOT_E];
__device__ float g_stats[512];              // [0..255] bn1 (sum,sumsq), [256..511] bn2
__device__ float g_scale1[DCH], g_shift1[DCH];
__device__ float g_scale2[DCH], g_shift2[DCH];

// ---------------- zero scratch ----------------
__global__ void zero_kernel() {
    int idx = blockIdx.x * blockDim.x + threadIdx.x;
    if (idx < N_NODES) { g_deg[idx] = 0; g_cur[idx] = 0; }
    if (idx < 512) g_stats[idx] = 0.f;
}

// ---------------- generic 128x128 GEMM: C = A@W + b ----------------
__global__ __launch_bounds__(256) void gemm128(
    const float* __restrict__ A, const float* __restrict__ W,
    const float* __restrict__ bias, float* __restrict__ C, int nrows)
{
    __shared__ float as[16][64];
    __shared__ float ws[16][128];
    int tid = threadIdx.x;
    int row0 = blockIdx.x * 64;
    int tcol = tid & 31, trow = tid >> 5;
    int c0 = tcol * 4, r0 = trow * 8;
    float4 acc[8];
#pragma unroll
    for (int r = 0; r < 8; r++) acc[r] = make_float4(0.f, 0.f, 0.f, 0.f);

    int lr = tid & 63, lkg = tid >> 6;
    for (int kb = 0; kb < 128; kb += 16) {
        float4 v = make_float4(0.f, 0.f, 0.f, 0.f);
        int grow = row0 + lr;
        if (grow < nrows) v = *(const float4*)(A + (size_t)grow * 128 + kb + lkg * 4);
        as[lkg * 4 + 0][lr] = v.x; as[lkg * 4 + 1][lr] = v.y;
        as[lkg * 4 + 2][lr] = v.z; as[lkg * 4 + 3][lr] = v.w;
#pragma unroll
        for (int it = 0; it < 2; it++) {
            int idx = tid + it * 256;
            int k = idx >> 5, cg = idx & 31;
            *(float4*)&ws[k][cg * 4] = *(const float4*)(W + (size_t)(kb + k) * 128 + cg * 4);
        }
        __syncthreads();
#pragma unroll
        for (int k = 0; k < 16; k++) {
            float4 w4  = *(float4*)&ws[k][c0];
            float4 alo = *(float4*)&as[k][r0];
            float4 ahi = *(float4*)&as[k][r0 + 4];
            float a[8] = {alo.x, alo.y, alo.z, alo.w, ahi.x, ahi.y, ahi.z, ahi.w};
#pragma unroll
            for (int r = 0; r < 8; r++) {
                acc[r].x += a[r] * w4.x; acc[r].y += a[r] * w4.y;
                acc[r].z += a[r] * w4.z; acc[r].w += a[r] * w4.w;
            }
        }
        __syncthreads();
    }
    float4 b4 = *(const float4*)(bias + c0);
#pragma unroll
    for (int r = 0; r < 8; r++) {
        int grow = row0 + r0 + r;
        if (grow < nrows) {
            float4 o;
            o.x = acc[r].x + b4.x; o.y = acc[r].y + b4.y;
            o.z = acc[r].z + b4.z; o.w = acc[r].w + b4.w;
            *(float4*)(C + (size_t)grow * 128 + c0) = o;
        }
    }
}

// ---------------- CSR build ----------------
__global__ void hist_kernel(const int* __restrict__ ei) {
    int t = blockIdx.x * blockDim.x + threadIdx.x;
    if (t >= TOT_E) return;
    int dst = (t < E_EDGES) ? ei[E_EDGES + t] : (t - E_EDGES);
    atomicAdd(&g_deg[dst], 1);
}

__global__ __launch_bounds__(1024) void scan_kernel() {
    __shared__ int sh[1024];
    int tid = threadIdx.x;
    const int CH = (N_NODES + 1023) >> 10;   // 49
    int start = tid * CH;
    int s = 0;
    for (int j = 0; j < CH; j++) { int idx = start + j; if (idx < N_NODES) s += g_deg[idx]; }
    int val = s;
    sh[tid] = val; __syncthreads();
    for (int off = 1; off < 1024; off <<= 1) {
        int v = (tid >= off) ? sh[tid - off] : 0;
        __syncthreads();
        val += v; sh[tid] = val; __syncthreads();
    }
    int run = val - s;   // exclusive prefix
    for (int j = 0; j < CH; j++) {
        int idx = start + j;
        if (idx < N_NODES) { g_off[idx] = run; run += g_deg[idx]; }
    }
    if (tid == 1023) g_off[N_NODES] = run;
}

__global__ void scatter_kernel(const int* __restrict__ ei) {
    int t = blockIdx.x * blockDim.x + threadIdx.x;
    if (t >= TOT_E) return;
    int dst = (t < E_EDGES) ? ei[E_EDGES + t] : (t - E_EDGES);
    int pos = atomicAdd(&g_cur[dst], 1);
    g_elist[g_off[dst] + pos] = t;
}

// ---------------- conv weight transpose: wext[(t*128+cin)*128 + cout] ----------------
__global__ void prep_wext(const float* __restrict__ conv_w) {
    int idx = blockIdx.x * blockDim.x + threadIdx.x;
    if (idx >= 384 * 128) return;
    int kext = idx >> 7;        // t*128 + cin
    int cout = idx & 127;
    int t = kext >> 7;
    int cin = kext & 127;
    g_wext[idx] = conv_w[cout * 384 + cin * 3 + t];
}

// ---------------- fused attention: warp per dst node, online softmax ----------------
__global__ __launch_bounds__(256) void attn_kernel(
    const float* __restrict__ x, const int* __restrict__ ei,
    const float* __restrict__ edge_attr, const float* __restrict__ W_e,
    const float* __restrict__ att, const float* __restrict__ bias_gat,
    const float* __restrict__ weight1)
{
    __shared__ float We_s[2048];
    __shared__ float att_s[128];
    __shared__ float bias_s[128];
    int tid = threadIdx.x;
    for (int idx = tid; idx < 2048; idx += 256) We_s[idx] = W_e[idx];
    if (tid < 128) { att_s[tid] = att[tid]; bias_s[tid] = bias_gat[tid]; }
    __syncthreads();

    int i = blockIdx.x * 8 + (tid >> 5);   // grid = 6250 -> exactly 50000 nodes
    int lane = tid & 31;
    int c0 = lane * 4;
    int base = g_off[i];
    int deg = g_off[i + 1] - base;

    const float4 xr4 = *(const float4*)(g_xr + (size_t)i * 128 + c0);
    float ax = att_s[c0], ay = att_s[c0 + 1], az = att_s[c0 + 2], aw = att_s[c0 + 3];
    float m = -3.0e38f, den = 0.f;
    float4 acc = make_float4(0.f, 0.f, 0.f, 0.f);

    for (int jj = 0; jj < deg; ++jj) {
        int e = g_elist[base + jj];
        int src = (e < E_EDGES) ? ei[e] : (e - E_EDGES);
        const float4 xl4 = *(const float4*)(g_xl + (size_t)src * 128 + c0);
        float mx = xl4.x + xr4.x, my = xl4.y + xr4.y;
        float mz = xl4.z + xr4.z, mw = xl4.w + xr4.w;
        if (e < E_EDGES) {
            const float* ea = edge_attr + (size_t)e * EDIM;
#pragma unroll
            for (int k = 0; k < EDIM; k++) {
                float ev = __ldg(ea + k);
                const float4 w = *(const float4*)&We_s[k * 128 + c0];
                mx += ev * w.x; my += ev * w.y; mz += ev * w.z; mw += ev * w.w;
            }
        }
        mx = (mx > 0.f) ? mx : 0.2f * mx;
        my = (my > 0.f) ? my : 0.2f * my;
        mz = (mz > 0.f) ? mz : 0.2f * mz;
        mw = (mw > 0.f) ? mw : 0.2f * mw;
        float part = mx * ax + my * ay + mz * az + mw * aw;
#pragma unroll
        for (int o = 16; o; o >>= 1) part += __shfl_xor_sync(0xffffffffu, part, o);
        float l = part;
        if (l > m) {
            float scl = __expf(m - l);
            den *= scl;
            acc.x *= scl; acc.y *= scl; acc.z *= scl; acc.w *= scl;
            m = l;
        }
        float p = __expf(l - m);
        den += p;
        acc.x += p * xl4.x; acc.y += p * xl4.y;
        acc.z += p * xl4.z; acc.w += p * xl4.w;
    }
    float inv = 1.f / den;
    // softmax(weight1)
    float a0 = weight1[0], a1 = weight1[1];
    float wm = fmaxf(a0, a1);
    float e0 = __expf(a0 - wm), e1 = __expf(a1 - wm);
    float is = 1.f / (e0 + e1);
    float w10 = e0 * is, w11 = e1 * is;

    const float4 xv = *(const float4*)(x + (size_t)i * 128 + c0);
    float4 o;
    o.x = w10 * xv.x + w11 * (acc.x * inv + bias_s[c0]);
    o.y = w10 * xv.y + w11 * (acc.y * inv + bias_s[c0 + 1]);
    o.z = w10 * xv.z + w11 * (acc.z * inv + bias_s[c0 + 2]);
    o.w = w10 * xv.w + w11 * (acc.w * inv + bias_s[c0 + 3]);
    *(float4*)(g_zpre + (size_t)i * 128 + c0) = o;
}

// ---------------- per-channel sum / sumsq reduction ----------------
__global__ __launch_bounds__(512) void bnstats(const float* __restrict__ z, float* __restrict__ stats) {
    int c = threadIdx.x & 127;
    int rof = threadIdx.x >> 7;   // 0..3
    int rows_per_block = (N_NODES + gridDim.x - 1) / gridDim.x;
    int r0 = blockIdx.x * rows_per_block;
    int r1 = min(r0 + rows_per_block, N_NODES);
    float s = 0.f, q = 0.f;
    for (int r = r0 + rof; r < r1; r += 4) {
        float v = z[(size_t)r * 128 + c];
        s += v; q += v * v;
    }
    atomicAdd(&stats[c], s);
    atomicAdd(&stats[128 + c], q);
}

__global__ void bn_finalize(const float* __restrict__ stats,
                            const float* __restrict__ gamma, const float* __restrict__ beta,
                            float* __restrict__ scale, float* __restrict__ shift)
{
    int c = threadIdx.x;
    float mu = stats[c] * (1.f / N_NODES);
    float var = stats[128 + c] * (1.f / N_NODES) - mu * mu;
    float rstd = rsqrtf(var + 1e-5f);
    float s = rstd * gamma[c];
    scale[c] = s;
    shift[c] = beta[c] - mu * s;
}

// ---------------- conv1d(k=3) as K=384 GEMM + mix + stash z2 ----------------
__global__ __launch_bounds__(256) void conv_kernel(const float* __restrict__ conv_b,
                                                   const float* __restrict__ weight2)
{
    __shared__ float zs[66][128];
    __shared__ float wt[16][128];
    __shared__ float sc_s[128], sh_s[128];
    int tid = threadIdx.x;
    int row0 = blockIdx.x * 64;
    if (tid < 128) { sc_s[tid] = g_scale1[tid]; sh_s[tid] = g_shift1[tid]; }
    __syncthreads();

    // load + normalize input tile rows [row0-1, row0+64]; zero pad outside [0,N)
    for (int idx = tid; idx < 66 * 32; idx += 256) {
        int rr = idx >> 5, cg = idx & 31;
        int grow = row0 - 1 + rr;
        float4 v = make_float4(0.f, 0.f, 0.f, 0.f);
        if (grow >= 0 && grow < N_NODES) {
            float4 z = *(const float4*)(g_zpre + (size_t)grow * 128 + cg * 4);
            int c = cg * 4;
            v.x = z.x * sc_s[c] + sh_s[c];
            v.y = z.y * sc_s[c + 1] + sh_s[c + 1];
            v.z = z.z * sc_s[c + 2] + sh_s[c + 2];
            v.w = z.w * sc_s[c + 3] + sh_s[c + 3];
        }
        *(float4*)&zs[rr][cg * 4] = v;
    }

    int tcol = tid & 31, trow = tid >> 5;
    int c0 = tcol * 4, r0 = trow * 8;
    float4 acc[8];
#pragma unroll
    for (int r = 0; r < 8; r++) acc[r] = make_float4(0.f, 0.f, 0.f, 0.f);

    for (int t = 0; t < 3; t++) {
        for (int kc = 0; kc < 8; kc++) {
            __syncthreads();
#pragma unroll
            for (int it = 0; it < 2; it++) {
                int idx = tid + it * 256;
                int k = idx >> 5, cg = idx & 31;
                *(float4*)&wt[k][cg * 4] =
                    *(const float4*)(g_wext + (size_t)(t * 128 + kc * 16 + k) * 128 + cg * 4);
            }
            __syncthreads();
#pragma unroll
            for (int kk = 0; kk < 16; kk += 4) {
                float4 a4[8];
#pragma unroll
                for (int r = 0; r < 8; r++)
                    a4[r] = *(float4*)&zs[r0 + r + t][kc * 16 + kk];
#pragma unroll
                for (int q = 0; q < 4; q++) {
                    float4 w4 = *(float4*)&wt[kk + q][c0];
#pragma unroll
                    for (int r = 0; r < 8; r++) {
                        float av = (q == 0) ? a4[r].x : (q == 1) ? a4[r].y
                                 : (q == 2) ? a4[r].z : a4[r].w;
                        acc[r].x += av * w4.x; acc[r].y += av * w4.y;
                        acc[r].z += av * w4.z; acc[r].w += av * w4.w;
                    }
                }
            }
        }
    }

    // softmax(weight2)
    float a0 = weight2[0], a1 = weight2[1];
    float wm = fmaxf(a0, a1);
    float e0 = __expf(a0 - wm), e1 = __expf(a1 - wm);
    float is = 1.f / (e0 + e1);
    float w20 = e0 * is, w21 = e1 * is;

    float4 b4 = *(const float4*)(conv_b + c0);
#pragma unroll
    for (int r = 0; r < 8; r++) {
        int grow = row0 + r0 + r;
        if (grow < N_NODES) {
            float4 z1;
            z1.x = acc[r].x + b4.x; z1.y = acc[r].y + b4.y;
            z1.z = acc[r].z + b4.z; z1.w = acc[r].w + b4.w;
            z1.x = (z1.x > 0.f) ? z1.x : 0.01f * z1.x;
            z1.y = (z1.y > 0.f) ? z1.y : 0.01f * z1.y;
            z1.z = (z1.z > 0.f) ? z1.z : 0.01f * z1.z;
            z1.w = (z1.w > 0.f) ? z1.w : 0.01f * z1.w;
            float4 zn = *(float4*)&zs[r0 + r + 1][c0];
            float4 o;
            o.x = w20 * zn.x + w21 * z1.x;
            o.y = w20 * zn.y + w21 * z1.y;
            o.z = w20 * zn.z + w21 * z1.z;
            o.w = w20 * zn.w + w21 * z1.w;
            *(float4*)(g_z2 + (size_t)grow * 128 + c0) = o;
        }
    }
}

// ---------------- final BN2 apply ----------------
__global__ void final_apply(float* __restrict__ out) {
    int idx = blockIdx.x * blockDim.x + threadIdx.x;   // over N*32 float4 groups
    if (idx >= N_NODES * 32) return;
    int cg = idx & 31;
    int c = cg * 4;
    float4 z = *(const float4*)(g_z2 + (size_t)idx * 4);
    float4 o;
    o.x = z.x * g_scale2[c]     + g_shift2[c];
    o.y = z.y * g_scale2[c + 1] + g_shift2[c + 1];
    o.z = z.z * g_scale2[c + 2] + g_shift2[c + 2];
    o.w = z.w * g_scale2[c + 3] + g_shift2[c + 3];
    *(float4*)(out + (size_t)idx * 4) = o;
}

// ---------------- launch ----------------
extern "C" void kernel_launch(void* const* d_in, const int* in_sizes, int n_in,
                              void* d_out, int out_size)
{
    const float* x         = (const float*)d_in[0];
    const int*   ei        = (const int*)d_in[1];
    const float* edge_attr = (const float*)d_in[2];
    const float* W_l       = (const float*)d_in[3];
    const float* b_l       = (const float*)d_in[4];
    const float* W_r       = (const float*)d_in[5];
    const float* b_r       = (const float*)d_in[6];
    const float* W_e       = (const float*)d_in[7];
    const float* att       = (const float*)d_in[8];
    const float* bias_gat  = (const float*)d_in[9];
    const float* weight1   = (const float*)d_in[10];
    const float* bn1_gamma = (const float*)d_in[11];
    const float* bn1_beta  = (const float*)d_in[12];
    const float* conv_w    = (const float*)d_in[13];
    const float* conv_b    = (const float*)d_in[14];
    const float* weight2   = (const float*)d_in[15];
    const float* bn2_gamma = (const float*)d_in[16];
    const float* bn2_beta  = (const float*)d_in[17];
    float* out = (float*)d_out;

    float *p_xl, *p_xr, *p_zpre, *p_z2, *p_stats;
    float *p_sc1, *p_sh1, *p_sc2, *p_sh2;
    cudaGetSymbolAddress((void**)&p_xl, g_xl);
    cudaGetSymbolAddress((void**)&p_xr, g_xr);
    cudaGetSymbolAddress((void**)&p_zpre, g_zpre);
    cudaGetSymbolAddress((void**)&p_z2, g_z2);
    cudaGetSymbolAddress((void**)&p_stats, g_stats);
    cudaGetSymbolAddress((void**)&p_sc1, g_scale1);
    cudaGetSymbolAddress((void**)&p_sh1, g_shift1);
    cudaGetSymbolAddress((void**)&p_sc2, g_scale2);
    cudaGetSymbolAddress((void**)&p_sh2, g_shift2);

    zero_kernel<<<(N_NODES + 255) / 256, 256>>>();
    gemm128<<<(N_NODES + 63) / 64, 256>>>(x, W_l, b_l, p_xl, N_NODES);
    gemm128<<<(N_NODES + 63) / 64, 256>>>(x, W_r, b_r, p_xr, N_NODES);
    hist_kernel<<<(TOT_E + 255) / 256, 256>>>(ei);
    scan_kernel<<<1, 1024>>>();
    scatter_kernel<<<(TOT_E + 255) / 256, 256>>>(ei);
    prep_wext<<<(384 * 128 + 255) / 256, 256>>>(conv_w);
    attn_kernel<<<N_NODES / 8, 256>>>(x, ei, edge_attr, W_e, att, bias_gat, weight1);
    bnstats<<<128, 512>>>(p_zpre, p_stats);
    bn_finalize<<<1, 128>>>(p_stats, bn1_gamma, bn1_beta, p_sc1, p_sh1);
    conv_kernel<<<(N_NODES + 63) / 64, 256>>>(conv_b, weight2);
    bnstats<<<128, 512>>>(p_z2, p_stats + 256);
    bn_finalize<<<1, 128>>>(p_stats + 256, bn2_gamma, bn2_beta, p_sc2, p_sh2);
    final_apply<<<(N_NODES * 32 + 255) / 256, 256>>>(out);
}

// round 2
// speedup vs baseline: 1.0027x; 1.0027x over previous
#include <cuda_runtime.h>

#define N_NODES 50000
#define E_EDGES 800000
#define TOT_E   (E_EDGES + N_NODES)
#define DCH     128
#define EDIM    16

// ---------------- device scratch (no allocs allowed) ----------------
__device__ float g_xl[N_NODES * DCH];
__device__ float g_xr[N_NODES * DCH];
__device__ float g_zpre[N_NODES * DCH];
__device__ float g_z2[N_NODES * DCH];
__device__ float g_wext[384 * DCH];
__device__ int   g_deg[N_NODES];
__device__ int   g_cur[N_NODES];
__device__ int   g_off[N_NODES + 1];
__device__ int   g_elist[TOT_E];
__device__ float g_stats[512];              // [0..255] bn1 (sum,sumsq), [256..511] bn2
__device__ float g_scale1[DCH], g_shift1[DCH];
__device__ float g_scale2[DCH], g_shift2[DCH];

// ---------------- zero scratch ----------------
__global__ void zero_kernel() {
    int idx = blockIdx.x * blockDim.x + threadIdx.x;
    if (idx < N_NODES) { g_deg[idx] = 0; g_cur[idx] = 0; }
    if (idx < 512) g_stats[idx] = 0.f;
}

// ---------------- generic 128x128 GEMM: C = A@W + b ----------------
__global__ __launch_bounds__(256) void gemm128(
    const float* __restrict__ A, const float* __restrict__ W,
    const float* __restrict__ bias, float* __restrict__ C, int nrows)
{
    __shared__ float as[16][64];
    __shared__ float ws[16][128];
    int tid = threadIdx.x;
    int row0 = blockIdx.x * 64;
    int tcol = tid & 31, trow = tid >> 5;
    int c0 = tcol * 4, r0 = trow * 8;
    float4 acc[8];
#pragma unroll
    for (int r = 0; r < 8; r++) acc[r] = make_float4(0.f, 0.f, 0.f, 0.f);

    int lr = tid & 63, lkg = tid >> 6;
    for (int kb = 0; kb < 128; kb += 16) {
        float4 v = make_float4(0.f, 0.f, 0.f, 0.f);
        int grow = row0 + lr;
        if (grow < nrows) v = *(const float4*)(A + (size_t)grow * 128 + kb + lkg * 4);
        as[lkg * 4 + 0][lr] = v.x; as[lkg * 4 + 1][lr] = v.y;
        as[lkg * 4 + 2][lr] = v.z; as[lkg * 4 + 3][lr] = v.w;
#pragma unroll
        for (int it = 0; it < 2; it++) {
            int idx = tid + it * 256;
            int k = idx >> 5, cg = idx & 31;
            *(float4*)&ws[k][cg * 4] = *(const float4*)(W + (size_t)(kb + k) * 128 + cg * 4);
        }
        __syncthreads();
#pragma unroll
        for (int k = 0; k < 16; k++) {
            float4 w4  = *(float4*)&ws[k][c0];
            float4 alo = *(float4*)&as[k][r0];
            float4 ahi = *(float4*)&as[k][r0 + 4];
            float a[8] = {alo.x, alo.y, alo.z, alo.w, ahi.x, ahi.y, ahi.z, ahi.w};
#pragma unroll
            for (int r = 0; r < 8; r++) {
                acc[r].x += a[r] * w4.x; acc[r].y += a[r] * w4.y;
                acc[r].z += a[r] * w4.z; acc[r].w += a[r] * w4.w;
            }
        }
        __syncthreads();
    }
    float4 b4 = *(const float4*)(bias + c0);
#pragma unroll
    for (int r = 0; r < 8; r++) {
        int grow = row0 + r0 + r;
        if (grow < nrows) {
            float4 o;
            o.x = acc[r].x + b4.x; o.y = acc[r].y + b4.y;
            o.z = acc[r].z + b4.z; o.w = acc[r].w + b4.w;
            *(float4*)(C + (size_t)grow * 128 + c0) = o;
        }
    }
}

// ---------------- CSR build ----------------
__global__ void hist_kernel(const int* __restrict__ ei) {
    int t = blockIdx.x * blockDim.x + threadIdx.x;
    if (t >= TOT_E) return;
    int dst = (t < E_EDGES) ? ei[E_EDGES + t] : (t - E_EDGES);
    atomicAdd(&g_deg[dst], 1);
}

__global__ __launch_bounds__(1024) void scan_kernel() {
    __shared__ int sh[1024];
    int tid = threadIdx.x;
    const int CH = (N_NODES + 1023) >> 10;   // 49
    int start = tid * CH;
    int s = 0;
    for (int j = 0; j < CH; j++) { int idx = start + j; if (idx < N_NODES) s += g_deg[idx]; }
    int val = s;
    sh[tid] = val; __syncthreads();
    for (int off = 1; off < 1024; off <<= 1) {
        int v = (tid >= off) ? sh[tid - off] : 0;
        __syncthreads();
        val += v; sh[tid] = val; __syncthreads();
    }
    int run = val - s;   // exclusive prefix
    for (int j = 0; j < CH; j++) {
        int idx = start + j;
        if (idx < N_NODES) { g_off[idx] = run; run += g_deg[idx]; }
    }
    if (tid == 1023) g_off[N_NODES] = run;
}

__global__ void scatter_kernel(const int* __restrict__ ei) {
    int t = blockIdx.x * blockDim.x + threadIdx.x;
    if (t >= TOT_E) return;
    int dst = (t < E_EDGES) ? ei[E_EDGES + t] : (t - E_EDGES);
    int pos = atomicAdd(&g_cur[dst], 1);
    g_elist[g_off[dst] + pos] = t;
}

// ---------------- conv weight transpose: wext[(t*128+cin)*128 + cout] ----------------
__global__ void prep_wext(const float* __restrict__ conv_w) {
    int idx = blockIdx.x * blockDim.x + threadIdx.x;
    if (idx >= 384 * 128) return;
    int kext = idx >> 7;        // t*128 + cin
    int cout = idx & 127;
    int t = kext >> 7;
    int cin = kext & 127;
    g_wext[idx] = conv_w[cout * 384 + cin * 3 + t];
}

// ---------------- fused attention: warp per dst node, online softmax ----------------
__global__ __launch_bounds__(256) void attn_kernel(
    const float* __restrict__ x, const int* __restrict__ ei,
    const float* __restrict__ edge_attr, const float* __restrict__ W_e,
    const float* __restrict__ att, const float* __restrict__ bias_gat,
    const float* __restrict__ weight1)
{
    __shared__ float We_s[2048];
    __shared__ float att_s[128];
    __shared__ float bias_s[128];
    int tid = threadIdx.x;
    for (int idx = tid; idx < 2048; idx += 256) We_s[idx] = W_e[idx];
    if (tid < 128) { att_s[tid] = att[tid]; bias_s[tid] = bias_gat[tid]; }
    __syncthreads();

    int i = blockIdx.x * 8 + (tid >> 5);   // grid = 6250 -> exactly 50000 nodes
    int lane = tid & 31;
    int c0 = lane * 4;
    int base = g_off[i];
    int deg = g_off[i + 1] - base;

    const float4 xr4 = *(const float4*)(g_xr + (size_t)i * 128 + c0);
    float ax = att_s[c0], ay = att_s[c0 + 1], az = att_s[c0 + 2], aw = att_s[c0 + 3];
    float m = -3.0e38f, den = 0.f;
    float4 acc = make_float4(0.f, 0.f, 0.f, 0.f);

    for (int jj = 0; jj < deg; ++jj) {
        int e = g_elist[base + jj];
        int src = (e < E_EDGES) ? ei[e] : (e - E_EDGES);
        const float4 xl4 = *(const float4*)(g_xl + (size_t)src * 128 + c0);
        float mx = xl4.x + xr4.x, my = xl4.y + xr4.y;
        float mz = xl4.z + xr4.z, mw = xl4.w + xr4.w;
        if (e < E_EDGES) {
            const float* ea = edge_attr + (size_t)e * EDIM;
#pragma unroll
            for (int k = 0; k < EDIM; k++) {
                float ev = __ldg(ea + k);
                const float4 w = *(const float4*)&We_s[k * 128 + c0];
                mx += ev * w.x; my += ev * w.y; mz += ev * w.z; mw += ev * w.w;
            }
        }
        mx = (mx > 0.f) ? mx : 0.2f * mx;
        my = (my > 0.f) ? my : 0.2f * my;
        mz = (mz > 0.f) ? mz : 0.2f * mz;
        mw = (mw > 0.f) ? mw : 0.2f * mw;
        float part = mx * ax + my * ay + mz * az + mw * aw;
#pragma unroll
        for (int o = 16; o; o >>= 1) part += __shfl_xor_sync(0xffffffffu, part, o);
        float l = part;
        if (l > m) {
            float scl = __expf(m - l);
            den *= scl;
            acc.x *= scl; acc.y *= scl; acc.z *= scl; acc.w *= scl;
            m = l;
        }
        float p = __expf(l - m);
        den += p;
        acc.x += p * xl4.x; acc.y += p * xl4.y;
        acc.z += p * xl4.z; acc.w += p * xl4.w;
    }
    float inv = 1.f / den;
    // softmax(weight1)
    float a0 = weight1[0], a1 = weight1[1];
    float wm = fmaxf(a0, a1);
    float e0 = __expf(a0 - wm), e1 = __expf(a1 - wm);
    float is = 1.f / (e0 + e1);
    float w10 = e0 * is, w11 = e1 * is;

    const float4 xv = *(const float4*)(x + (size_t)i * 128 + c0);
    float4 o;
    o.x = w10 * xv.x + w11 * (acc.x * inv + bias_s[c0]);
    o.y = w10 * xv.y + w11 * (acc.y * inv + bias_s[c0 + 1]);
    o.z = w10 * xv.z + w11 * (acc.z * inv + bias_s[c0 + 2]);
    o.w = w10 * xv.w + w11 * (acc.w * inv + bias_s[c0 + 3]);
    *(float4*)(g_zpre + (size_t)i * 128 + c0) = o;
}

// ---------------- per-channel sum / sumsq reduction ----------------
__global__ __launch_bounds__(512) void bnstats(const float* __restrict__ z, float* __restrict__ stats) {
    int c = threadIdx.x & 127;
    int rof = threadIdx.x >> 7;   // 0..3
    int rows_per_block = (N_NODES + gridDim.x - 1) / gridDim.x;
    int r0 = blockIdx.x * rows_per_block;
    int r1 = min(r0 + rows_per_block, N_NODES);
    float s = 0.f, q = 0.f;
    for (int r = r0 + rof; r < r1; r += 4) {
        float v = z[(size_t)r * 128 + c];
        s += v; q += v * v;
    }
    atomicAdd(&stats[c], s);
    atomicAdd(&stats[128 + c], q);
}

__global__ void bn_finalize(const float* __restrict__ stats,
                            const float* __restrict__ gamma, const float* __restrict__ beta,
                            float* __restrict__ scale, float* __restrict__ shift)
{
    int c = threadIdx.x;
    float mu = stats[c] * (1.f / N_NODES);
    float var = stats[128 + c] * (1.f / N_NODES) - mu * mu;
    float rstd = rsqrtf(var + 1e-5f);
    float s = rstd * gamma[c];
    scale[c] = s;
    shift[c] = beta[c] - mu * s;
}

// ---------------- conv1d(k=3) as K=384 GEMM + mix + stash z2 ----------------
__global__ __launch_bounds__(256) void conv_kernel(const float* __restrict__ conv_b,
                                                   const float* __restrict__ weight2)
{
    __shared__ float zs[66][128];
    __shared__ float wt[16][128];
    __shared__ float sc_s[128], sh_s[128];
    int tid = threadIdx.x;
    int row0 = blockIdx.x * 64;
    if (tid < 128) { sc_s[tid] = g_scale1[tid]; sh_s[tid] = g_shift1[tid]; }
    __syncthreads();

    // load + normalize input tile rows [row0-1, row0+64]; zero pad outside [0,N)
    for (int idx = tid; idx < 66 * 32; idx += 256) {
        int rr = idx >> 5, cg = idx & 31;
        int grow = row0 - 1 + rr;
        float4 v = make_float4(0.f, 0.f, 0.f, 0.f);
        if (grow >= 0 && grow < N_NODES) {
            float4 z = *(const float4*)(g_zpre + (size_t)grow * 128 + cg * 4);
            int c = cg * 4;
            v.x = z.x * sc_s[c] + sh_s[c];
            v.y = z.y * sc_s[c + 1] + sh_s[c + 1];
            v.z = z.z * sc_s[c + 2] + sh_s[c + 2];
            v.w = z.w * sc_s[c + 3] + sh_s[c + 3];
        }
        *(float4*)&zs[rr][cg * 4] = v;
    }

    int tcol = tid & 31, trow = tid >> 5;
    int c0 = tcol * 4, r0 = trow * 8;
    float4 acc[8];
#pragma unroll
    for (int r = 0; r < 8; r++) acc[r] = make_float4(0.f, 0.f, 0.f, 0.f);

    for (int t = 0; t < 3; t++) {
        for (int kc = 0; kc < 8; kc++) {
            __syncthreads();
#pragma unroll
            for (int it = 0; it < 2; it++) {
                int idx = tid + it * 256;
                int k = idx >> 5, cg = idx & 31;
                *(float4*)&wt[k][cg * 4] =
                    *(const float4*)(g_wext + (size_t)(t * 128 + kc * 16 + k) * 128 + cg * 4);
            }
            __syncthreads();
#pragma unroll
            for (int kk = 0; kk < 16; kk += 4) {
                float4 a4[8];
#pragma unroll
                for (int r = 0; r < 8; r++)
                    a4[r] = *(float4*)&zs[r0 + r + t][kc * 16 + kk];
#pragma unroll
                for (int q = 0; q < 4; q++) {
                    float4 w4 = *(float4*)&wt[kk + q][c0];
#pragma unroll
                    for (int r = 0; r < 8; r++) {
                        float av = (q == 0) ? a4[r].x : (q == 1) ? a4[r].y
                                 : (q == 2) ? a4[r].z : a4[r].w;
                        acc[r].x += av * w4.x; acc[r].y += av * w4.y;
                        acc[r].z += av * w4.z; acc[r].w += av * w4.w;
                    }
                }
            }
        }
    }

    // softmax(weight2)
    float a0 = weight2[0], a1 = weight2[1];
    float wm = fmaxf(a0, a1);
    float e0 = __expf(a0 - wm), e1 = __expf(a1 - wm);
    float is = 1.f / (e0 + e1);
    float w20 = e0 * is, w21 = e1 * is;

    float4 b4 = *(const float4*)(conv_b + c0);
#pragma unroll
    for (int r = 0; r < 8; r++) {
        int grow = row0 + r0 + r;
        if (grow < N_NODES) {
            float4 z1;
            z1.x = acc[r].x + b4.x; z1.y = acc[r].y + b4.y;
            z1.z = acc[r].z + b4.z; z1.w = acc[r].w + b4.w;
            z1.x = (z1.x > 0.f) ? z1.x : 0.01f * z1.x;
            z1.y = (z1.y > 0.f) ? z1.y : 0.01f * z1.y;
            z1.z = (z1.z > 0.f) ? z1.z : 0.01f * z1.z;
            z1.w = (z1.w > 0.f) ? z1.w : 0.01f * z1.w;
            float4 zn = *(float4*)&zs[r0 + r + 1][c0];
            float4 o;
            o.x = w20 * zn.x + w21 * z1.x;
            o.y = w20 * zn.y + w21 * z1.y;
            o.z = w20 * zn.z + w21 * z1.z;
            o.w = w20 * zn.w + w21 * z1.w;
            *(float4*)(g_z2 + (size_t)grow * 128 + c0) = o;
        }
    }
}

// ---------------- final BN2 apply ----------------
__global__ void final_apply(float* __restrict__ out) {
    int idx = blockIdx.x * blockDim.x + threadIdx.x;   // over N*32 float4 groups
    if (idx >= N_NODES * 32) return;
    int cg = idx & 31;
    int c = cg * 4;
    float4 z = *(const float4*)(g_z2 + (size_t)idx * 4);
    float4 o;
    o.x = z.x * g_scale2[c]     + g_shift2[c];
    o.y = z.y * g_scale2[c + 1] + g_shift2[c + 1];
    o.z = z.z * g_scale2[c + 2] + g_shift2[c + 2];
    o.w = z.w * g_scale2[c + 3] + g_shift2[c + 3];
    *(float4*)(out + (size_t)idx * 4) = o;
}

// ---------------- launch ----------------
extern "C" void kernel_launch(void* const* d_in, const int* in_sizes, int n_in,
                              void* d_out, int out_size)
{
    const float* x         = (const float*)d_in[0];
    const int*   ei        = (const int*)d_in[1];
    const float* edge_attr = (const float*)d_in[2];
    const float* W_l       = (const float*)d_in[3];
    const float* b_l       = (const float*)d_in[4];
    const float* W_r       = (const float*)d_in[5];
    const float* b_r       = (const float*)d_in[6];
    const float* W_e       = (const float*)d_in[7];
    const float* att       = (const float*)d_in[8];
    const float* bias_gat  = (const float*)d_in[9];
    const float* weight1   = (const float*)d_in[10];
    const float* bn1_gamma = (const float*)d_in[11];
    const float* bn1_beta  = (const float*)d_in[12];
    const float* conv_w    = (const float*)d_in[13];
    const float* conv_b    = (const float*)d_in[14];
    const float* weight2   = (const float*)d_in[15];
    const float* bn2_gamma = (const float*)d_in[16];
    const float* bn2_beta  = (const float*)d_in[17];
    float* out = (float*)d_out;

    float *p_xl, *p_xr, *p_zpre, *p_z2, *p_stats;
    float *p_sc1, *p_sh1, *p_sc2, *p_sh2;
    cudaGetSymbolAddress((void**)&p_xl, g_xl);
    cudaGetSymbolAddress((void**)&p_xr, g_xr);
    cudaGetSymbolAddress((void**)&p_zpre, g_zpre);
    cudaGetSymbolAddress((void**)&p_z2, g_z2);
    cudaGetSymbolAddress((void**)&p_stats, g_stats);
    cudaGetSymbolAddress((void**)&p_sc1, g_scale1);
    cudaGetSymbolAddress((void**)&p_sh1, g_shift1);
    cudaGetSymbolAddress((void**)&p_sc2, g_scale2);
    cudaGetSymbolAddress((void**)&p_sh2, g_shift2);

    zero_kernel<<<(N_NODES + 255) / 256, 256>>>();
    gemm128<<<(N_NODES + 63) / 64, 256>>>(x, W_l, b_l, p_xl, N_NODES);
    gemm128<<<(N_NODES + 63) / 64, 256>>>(x, W_r, b_r, p_xr, N_NODES);
    hist_kernel<<<(TOT_E + 255) / 256, 256>>>(ei);
    scan_kernel<<<1, 1024>>>();
    scatter_kernel<<<(TOT_E + 255) / 256, 256>>>(ei);
    prep_wext<<<(384 * 128 + 255) / 256, 256>>>(conv_w);
    attn_kernel<<<N_NODES / 8, 256>>>(x, ei, edge_attr, W_e, att, bias_gat, weight1);
    bnstats<<<128, 512>>>(p_zpre, p_stats);
    bn_finalize<<<1, 128>>>(p_stats, bn1_gamma, bn1_beta, p_sc1, p_sh1);
    conv_kernel<<<(N_NODES + 63) / 64, 256>>>(conv_b, weight2);
    bnstats<<<128, 512>>>(p_z2, p_stats + 256);
    bn_finalize<<<1, 128>>>(p_stats + 256, bn2_gamma, bn2_beta, p_sc2, p_sh2);
    final_apply<<<(N_NODES * 32 + 255) / 256, 256>>>(out);
}

// round 3
// speedup vs baseline: 1.0066x; 1.0040x over previous
#include <cuda_runtime.h>

#define N_NODES 50000
#define E_EDGES 800000
#define TOT_E   (E_EDGES + N_NODES)
#define DCH     128
#define EDIM    16

// ---------------- device scratch (no allocs allowed) ----------------
__device__ float g_xl[N_NODES * DCH];
__device__ float g_xr[N_NODES * DCH];
__device__ float g_zpre[N_NODES * DCH];
__device__ float g_z2[N_NODES * DCH];
__device__ float g_wext[384 * DCH];
__device__ int   g_deg[N_NODES];
__device__ int   g_cur[N_NODES];
__device__ int   g_off[N_NODES + 1];
__device__ int   g_elist[TOT_E];
__device__ float g_stats[512];              // [0..255] bn1 (sum,sumsq), [256..511] bn2
__device__ float g_scale1[DCH], g_shift1[DCH];
__device__ float g_scale2[DCH], g_shift2[DCH];

// ---------------- zero scratch ----------------
__global__ void zero_kernel() {
    int idx = blockIdx.x * blockDim.x + threadIdx.x;
    if (idx < N_NODES) { g_deg[idx] = 0; g_cur[idx] = 0; }
    if (idx < 512) g_stats[idx] = 0.f;
}

// ---------------- generic 128x128 GEMM: C = A@W + b ----------------
__global__ __launch_bounds__(256) void gemm128(
    const float* __restrict__ A, const float* __restrict__ W,
    const float* __restrict__ bias, float* __restrict__ C, int nrows)
{
    __shared__ float as[16][64];
    __shared__ float ws[16][128];
    int tid = threadIdx.x;
    int row0 = blockIdx.x * 64;
    int tcol = tid & 31, trow = tid >> 5;
    int c0 = tcol * 4, r0 = trow * 8;
    float4 acc[8];
#pragma unroll
    for (int r = 0; r < 8; r++) acc[r] = make_float4(0.f, 0.f, 0.f, 0.f);

    int lr = tid & 63, lkg = tid >> 6;
    for (int kb = 0; kb < 128; kb += 16) {
        float4 v = make_float4(0.f, 0.f, 0.f, 0.f);
        int grow = row0 + lr;
        if (grow < nrows) v = *(const float4*)(A + (size_t)grow * 128 + kb + lkg * 4);
        as[lkg * 4 + 0][lr] = v.x; as[lkg * 4 + 1][lr] = v.y;
        as[lkg * 4 + 2][lr] = v.z; as[lkg * 4 + 3][lr] = v.w;
#pragma unroll
        for (int it = 0; it < 2; it++) {
            int idx = tid + it * 256;
            int k = idx >> 5, cg = idx & 31;
            *(float4*)&ws[k][cg * 4] = *(const float4*)(W + (size_t)(kb + k) * 128 + cg * 4);
        }
        __syncthreads();
#pragma unroll
        for (int k = 0; k < 16; k++) {
            float4 w4  = *(float4*)&ws[k][c0];
            float4 alo = *(float4*)&as[k][r0];
            float4 ahi = *(float4*)&as[k][r0 + 4];
            float a[8] = {alo.x, alo.y, alo.z, alo.w, ahi.x, ahi.y, ahi.z, ahi.w};
#pragma unroll
            for (int r = 0; r < 8; r++) {
                acc[r].x += a[r] * w4.x; acc[r].y += a[r] * w4.y;
                acc[r].z += a[r] * w4.z; acc[r].w += a[r] * w4.w;
            }
        }
        __syncthreads();
    }
    float4 b4 = *(const float4*)(bias + c0);
#pragma unroll
    for (int r = 0; r < 8; r++) {
        int grow = row0 + r0 + r;
        if (grow < nrows) {
            float4 o;
            o.x = acc[r].x + b4.x; o.y = acc[r].y + b4.y;
            o.z = acc[r].z + b4.z; o.w = acc[r].w + b4.w;
            *(float4*)(C + (size_t)grow * 128 + c0) = o;
        }
    }
}

// ---------------- CSR build ----------------
__global__ void hist_kernel(const int* __restrict__ ei) {
    int t = blockIdx.x * blockDim.x + threadIdx.x;
    if (t >= TOT_E) return;
    int dst = (t < E_EDGES) ? ei[E_EDGES + t] : (t - E_EDGES);
    atomicAdd(&g_deg[dst], 1);
}

__global__ __launch_bounds__(1024) void scan_kernel() {
    __shared__ int sh[1024];
    int tid = threadIdx.x;
    const int CH = (N_NODES + 1023) >> 10;   // 49
    int start = tid * CH;
    int s = 0;
    for (int j = 0; j < CH; j++) { int idx = start + j; if (idx < N_NODES) s += g_deg[idx]; }
    int val = s;
    sh[tid] = val; __syncthreads();
    for (int off = 1; off < 1024; off <<= 1) {
        int v = (tid >= off) ? sh[tid - off] : 0;
        __syncthreads();
        val += v; sh[tid] = val; __syncthreads();
    }
    int run = val - s;   // exclusive prefix
    for (int j = 0; j < CH; j++) {
        int idx = start + j;
        if (idx < N_NODES) { g_off[idx] = run; run += g_deg[idx]; }
    }
    if (tid == 1023) g_off[N_NODES] = run;
}

__global__ void scatter_kernel(const int* __restrict__ ei) {
    int t = blockIdx.x * blockDim.x + threadIdx.x;
    if (t >= TOT_E) return;
    int dst = (t < E_EDGES) ? ei[E_EDGES + t] : (t - E_EDGES);
    int pos = atomicAdd(&g_cur[dst], 1);
    g_elist[g_off[dst] + pos] = t;
}

// ---------------- conv weight transpose: wext[(t*128+cin)*128 + cout] ----------------
__global__ void prep_wext(const float* __restrict__ conv_w) {
    int idx = blockIdx.x * blockDim.x + threadIdx.x;
    if (idx >= 384 * 128) return;
    int kext = idx >> 7;        // t*128 + cin
    int cout = idx & 127;
    int t = kext >> 7;
    int cin = kext & 127;
    g_wext[idx] = conv_w[cout * 384 + cin * 3 + t];
}

// ---------------- fused attention: warp per dst node, online softmax ----------------
__global__ __launch_bounds__(256) void attn_kernel(
    const float* __restrict__ x, const int* __restrict__ ei,
    const float* __restrict__ edge_attr, const float* __restrict__ W_e,
    const float* __restrict__ att, const float* __restrict__ bias_gat,
    const float* __restrict__ weight1)
{
    __shared__ float We_s[2048];
    __shared__ float att_s[128];
    __shared__ float bias_s[128];
    int tid = threadIdx.x;
    for (int idx = tid; idx < 2048; idx += 256) We_s[idx] = W_e[idx];
    if (tid < 128) { att_s[tid] = att[tid]; bias_s[tid] = bias_gat[tid]; }
    __syncthreads();

    int i = blockIdx.x * 8 + (tid >> 5);   // grid = 6250 -> exactly 50000 nodes
    int lane = tid & 31;
    int c0 = lane * 4;
    int base = g_off[i];
    int deg = g_off[i + 1] - base;

    const float4 xr4 = *(const float4*)(g_xr + (size_t)i * 128 + c0);
    float ax = att_s[c0], ay = att_s[c0 + 1], az = att_s[c0 + 2], aw = att_s[c0 + 3];
    float m = -3.0e38f, den = 0.f;
    float4 acc = make_float4(0.f, 0.f, 0.f, 0.f);

    for (int jj = 0; jj < deg; ++jj) {
        int e = g_elist[base + jj];
        int src = (e < E_EDGES) ? ei[e] : (e - E_EDGES);
        const float4 xl4 = *(const float4*)(g_xl + (size_t)src * 128 + c0);
        float mx = xl4.x + xr4.x, my = xl4.y + xr4.y;
        float mz = xl4.z + xr4.z, mw = xl4.w + xr4.w;
        if (e < E_EDGES) {
            const float* ea = edge_attr + (size_t)e * EDIM;
#pragma unroll
            for (int k = 0; k < EDIM; k++) {
                float ev = __ldg(ea + k);
                const float4 w = *(const float4*)&We_s[k * 128 + c0];
                mx += ev * w.x; my += ev * w.y; mz += ev * w.z; mw += ev * w.w;
            }
        }
        mx = (mx > 0.f) ? mx : 0.2f * mx;
        my = (my > 0.f) ? my : 0.2f * my;
        mz = (mz > 0.f) ? mz : 0.2f * mz;
        mw = (mw > 0.f) ? mw : 0.2f * mw;
        float part = mx * ax + my * ay + mz * az + mw * aw;
#pragma unroll
        for (int o = 16; o; o >>= 1) part += __shfl_xor_sync(0xffffffffu, part, o);
        float l = part;
        if (l > m) {
            float scl = __expf(m - l);
            den *= scl;
            acc.x *= scl; acc.y *= scl; acc.z *= scl; acc.w *= scl;
            m = l;
        }
        float p = __expf(l - m);
        den += p;
        acc.x += p * xl4.x; acc.y += p * xl4.y;
        acc.z += p * xl4.z; acc.w += p * xl4.w;
    }
    float inv = 1.f / den;
    // softmax(weight1)
    float a0 = weight1[0], a1 = weight1[1];
    float wm = fmaxf(a0, a1);
    float e0 = __expf(a0 - wm), e1 = __expf(a1 - wm);
    float is = 1.f / (e0 + e1);
    float w10 = e0 * is, w11 = e1 * is;

    const float4 xv = *(const float4*)(x + (size_t)i * 128 + c0);
    float4 o;
    o.x = w10 * xv.x + w11 * (acc.x * inv + bias_s[c0]);
    o.y = w10 * xv.y + w11 * (acc.y * inv + bias_s[c0 + 1]);
    o.z = w10 * xv.z + w11 * (acc.z * inv + bias_s[c0 + 2]);
    o.w = w10 * xv.w + w11 * (acc.w * inv + bias_s[c0 + 3]);
    *(float4*)(g_zpre + (size_t)i * 128 + c0) = o;
}

// ---------------- per-channel sum / sumsq reduction ----------------
__global__ __launch_bounds__(512) void bnstats(const float* __restrict__ z, float* __restrict__ stats) {
    int c = threadIdx.x & 127;
    int rof = threadIdx.x >> 7;   // 0..3
    int rows_per_block = (N_NODES + gridDim.x - 1) / gridDim.x;
    int r0 = blockIdx.x * rows_per_block;
    int r1 = min(r0 + rows_per_block, N_NODES);
    float s = 0.f, q = 0.f;
    for (int r = r0 + rof; r < r1; r += 4) {
        float v = z[(size_t)r * 128 + c];
        s += v; q += v * v;
    }
    atomicAdd(&stats[c], s);
    atomicAdd(&stats[128 + c], q);
}

__global__ void bn_finalize(const float* __restrict__ stats,
                            const float* __restrict__ gamma, const float* __restrict__ beta,
                            float* __restrict__ scale, float* __restrict__ shift)
{
    int c = threadIdx.x;
    float mu = stats[c] * (1.f / N_NODES);
    float var = stats[128 + c] * (1.f / N_NODES) - mu * mu;
    float rstd = rsqrtf(var + 1e-5f);
    float s = rstd * gamma[c];
    scale[c] = s;
    shift[c] = beta[c] - mu * s;
}

// ---------------- conv1d(k=3) as K=384 GEMM + mix + stash z2 ----------------
__global__ __launch_bounds__(256) void conv_kernel(const float* __restrict__ conv_b,
                                                   const float* __restrict__ weight2)
{
    __shared__ float zs[66][128];
    __shared__ float wt[16][128];
    __shared__ float sc_s[128], sh_s[128];
    int tid = threadIdx.x;
    int row0 = blockIdx.x * 64;
    if (tid < 128) { sc_s[tid] = g_scale1[tid]; sh_s[tid] = g_shift1[tid]; }
    __syncthreads();

    // load + normalize input tile rows [row0-1, row0+64]; zero pad outside [0,N)
    for (int idx = tid; idx < 66 * 32; idx += 256) {
        int rr = idx >> 5, cg = idx & 31;
        int grow = row0 - 1 + rr;
        float4 v = make_float4(0.f, 0.f, 0.f, 0.f);
        if (grow >= 0 && grow < N_NODES) {
            float4 z = *(const float4*)(g_zpre + (size_t)grow * 128 + cg * 4);
            int c = cg * 4;
            v.x = z.x * sc_s[c] + sh_s[c];
            v.y = z.y * sc_s[c + 1] + sh_s[c + 1];
            v.z = z.z * sc_s[c + 2] + sh_s[c + 2];
            v.w = z.w * sc_s[c + 3] + sh_s[c + 3];
        }
        *(float4*)&zs[rr][cg * 4] = v;
    }

    int tcol = tid & 31, trow = tid >> 5;
    int c0 = tcol * 4, r0 = trow * 8;
    float4 acc[8];
#pragma unroll
    for (int r = 0; r < 8; r++) acc[r] = make_float4(0.f, 0.f, 0.f, 0.f);

    for (int t = 0; t < 3; t++) {
        for (int kc = 0; kc < 8; kc++) {
            __syncthreads();
#pragma unroll
            for (int it = 0; it < 2; it++) {
                int idx = tid + it * 256;
                int k = idx >> 5, cg = idx & 31;
                *(float4*)&wt[k][cg * 4] =
                    *(const float4*)(g_wext + (size_t)(t * 128 + kc * 16 + k) * 128 + cg * 4);
            }
            __syncthreads();
#pragma unroll
            for (int kk = 0; kk < 16; kk += 4) {
                float4 a4[8];
#pragma unroll
                for (int r = 0; r < 8; r++)
                    a4[r] = *(float4*)&zs[r0 + r + t][kc * 16 + kk];
#pragma unroll
                for (int q = 0; q < 4; q++) {
                    float4 w4 = *(float4*)&wt[kk + q][c0];
#pragma unroll
                    for (int r = 0; r < 8; r++) {
                        float av = (q == 0) ? a4[r].x : (q == 1) ? a4[r].y
                                 : (q == 2) ? a4[r].z : a4[r].w;
                        acc[r].x += av * w4.x; acc[r].y += av * w4.y;
                        acc[r].z += av * w4.z; acc[r].w += av * w4.w;
                    }
                }
            }
        }
    }

    // softmax(weight2)
    float a0 = weight2[0], a1 = weight2[1];
    float wm = fmaxf(a0, a1);
    float e0 = __expf(a0 - wm), e1 = __expf(a1 - wm);
    float is = 1.f / (e0 + e1);
    float w20 = e0 * is, w21 = e1 * is;

    float4 b4 = *(const float4*)(conv_b + c0);
#pragma unroll
    for (int r = 0; r < 8; r++) {
        int grow = row0 + r0 + r;
        if (grow < N_NODES) {
            float4 z1;
            z1.x = acc[r].x + b4.x; z1.y = acc[r].y + b4.y;
            z1.z = acc[r].z + b4.z; z1.w = acc[r].w + b4.w;
            z1.x = (z1.x > 0.f) ? z1.x : 0.01f * z1.x;
            z1.y = (z1.y > 0.f) ? z1.y : 0.01f * z1.y;
            z1.z = (z1.z > 0.f) ? z1.z : 0.01f * z1.z;
            z1.w = (z1.w > 0.f) ? z1.w : 0.01f * z1.w;
            float4 zn = *(float4*)&zs[r0 + r + 1][c0];
            float4 o;
            o.x = w20 * zn.x + w21 * z1.x;
            o.y = w20 * zn.y + w21 * z1.y;
            o.z = w20 * zn.z + w21 * z1.z;
            o.w = w20 * zn.w + w21 * z1.w;
            *(float4*)(g_z2 + (size_t)grow * 128 + c0) = o;
        }
    }
}

// ---------------- final BN2 apply ----------------
__global__ void final_apply(float* __restrict__ out) {
    int idx = blockIdx.x * blockDim.x + threadIdx.x;   // over N*32 float4 groups
    if (idx >= N_NODES * 32) return;
    int cg = idx & 31;
    int c = cg * 4;
    float4 z = *(const float4*)(g_z2 + (size_t)idx * 4);
    float4 o;
    o.x = z.x * g_scale2[c]     + g_shift2[c];
    o.y = z.y * g_scale2[c + 1] + g_shift2[c + 1];
    o.z = z.z * g_scale2[c + 2] + g_shift2[c + 2];
    o.w = z.w * g_scale2[c + 3] + g_shift2[c + 3];
    *(float4*)(out + (size_t)idx * 4) = o;
}

// ---------------- launch ----------------
extern "C" void kernel_launch(void* const* d_in, const int* in_sizes, int n_in,
                              void* d_out, int out_size)
{
    const float* x         = (const float*)d_in[0];
    const int*   ei        = (const int*)d_in[1];
    const float* edge_attr = (const float*)d_in[2];
    const float* W_l       = (const float*)d_in[3];
    const float* b_l       = (const float*)d_in[4];
    const float* W_r       = (const float*)d_in[5];
    const float* b_r       = (const float*)d_in[6];
    const float* W_e       = (const float*)d_in[7];
    const float* att       = (const float*)d_in[8];
    const float* bias_gat  = (const float*)d_in[9];
    const float* weight1   = (const float*)d_in[10];
    const float* bn1_gamma = (const float*)d_in[11];
    const float* bn1_beta  = (const float*)d_in[12];
    const float* conv_w    = (const float*)d_in[13];
    const float* conv_b    = (const float*)d_in[14];
    const float* weight2   = (const float*)d_in[15];
    const float* bn2_gamma = (const float*)d_in[16];
    const float* bn2_beta  = (const float*)d_in[17];
    float* out = (float*)d_out;

    float *p_xl, *p_xr, *p_zpre, *p_z2, *p_stats;
    float *p_sc1, *p_sh1, *p_sc2, *p_sh2;
    cudaGetSymbolAddress((void**)&p_xl, g_xl);
    cudaGetSymbolAddress((void**)&p_xr, g_xr);
    cudaGetSymbolAddress((void**)&p_zpre, g_zpre);
    cudaGetSymbolAddress((void**)&p_z2, g_z2);
    cudaGetSymbolAddress((void**)&p_stats, g_stats);
    cudaGetSymbolAddress((void**)&p_sc1, g_scale1);
    cudaGetSymbolAddress((void**)&p_sh1, g_shift1);
    cudaGetSymbolAddress((void**)&p_sc2, g_scale2);
    cudaGetSymbolAddress((void**)&p_sh2, g_shift2);

    zero_kernel<<<(N_NODES + 255) / 256, 256>>>();
    gemm128<<<(N_NODES + 63) / 64, 256>>>(x, W_l, b_l, p_xl, N_NODES);
    gemm128<<<(N_NODES + 63) / 64, 256>>>(x, W_r, b_r, p_xr, N_NODES);
    hist_kernel<<<(TOT_E + 255) / 256, 256>>>(ei);
    scan_kernel<<<1, 1024>>>();
    scatter_kernel<<<(TOT_E + 255) / 256, 256>>>(ei);
    prep_wext<<<(384 * 128 + 255) / 256, 256>>>(conv_w);
    attn_kernel<<<N_NODES / 8, 256>>>(x, ei, edge_attr, W_e, att, bias_gat, weight1);
    bnstats<<<128, 512>>>(p_zpre, p_stats);
    bn_finalize<<<1, 128>>>(p_stats, bn1_gamma, bn1_beta, p_sc1, p_sh1);
    conv_kernel<<<(N_NODES + 63) / 64, 256>>>(conv_b, weight2);
    bnstats<<<128, 512>>>(p_z2, p_stats + 256);
    bn_finalize<<<1, 128>>>(p_stats + 256, bn2_gamma, bn2_beta, p_sc2, p_sh2);
    final_apply<<<(N_NODES * 32 + 255) / 256, 256>>>(out);
}